// round 4
// baseline (speedup 1.0000x reference)
#include <cuda_runtime.h>
#include <cuda_bf16.h>

// Problem constants (fixed by dataset)
#define NMAX 50000
#define EMAX 800000
#define CIN  512
#define CHID 128
#define COUT 64

// ---------------- device scratch (static, allocation-free) ----------------
__device__ int   g_cnt[NMAX];        // in-degree (excl self loop)
__device__ int   g_offsets[NMAX+1];  // CSR offsets by dst
__device__ int   g_cursor[NMAX];     // fill cursors
__device__ int   g_col[EMAX];        // src node per edge, grouped by dst
__device__ float g_dinv[NMAX];       // deg^-1/2 (deg includes self loop)
__device__ float g_h1[NMAX*CHID];    // (x@W1)*dinv[row]
__device__ float g_z1[NMAX*CHID];    // relu(agg + b1)
__device__ float g_h2[NMAX*COUT];    // (z1@W2)*dinv[row]
__device__ float g_z2[NMAX*COUT];    // agg + b2

// ---------------- graph preprocessing ----------------
__global__ void k_zero_cnt(int n) {
    int i = blockIdx.x * blockDim.x + threadIdx.x;
    if (i < n) g_cnt[i] = 0;
}

__global__ void k_count(const int* __restrict__ ei, int e) {
    int i = blockIdx.x * blockDim.x + threadIdx.x;
    if (i < e) atomicAdd(&g_cnt[ei[e + i]], 1);   // dst row
}

__global__ void k_dinv(int n) {
    int i = blockIdx.x * blockDim.x + threadIdx.x;
    if (i < n) g_dinv[i] = rsqrtf((float)(g_cnt[i] + 1));  // +1 self loop
}

// single-block exclusive scan over g_cnt -> g_offsets, g_cursor
__global__ void k_scan(int n, int e) {
    __shared__ int sdata[1024];
    int tid = threadIdx.x;
    int chunk = (n + 1023) / 1024;
    int start = tid * chunk;
    int end   = min(start + chunk, n);
    int s = 0;
    for (int i = start; i < end; i++) s += g_cnt[i];
    sdata[tid] = s;
    __syncthreads();
    for (int off = 1; off < 1024; off <<= 1) {
        int v = 0;
        if (tid >= off) v = sdata[tid - off];
        __syncthreads();
        sdata[tid] += v;
        __syncthreads();
    }
    int run = sdata[tid] - s;  // exclusive prefix
    for (int i = start; i < end; i++) {
        g_offsets[i] = run;
        g_cursor[i]  = run;
        run += g_cnt[i];
    }
    if (tid == 0) g_offsets[n] = sdata[1023];
}

__global__ void k_fill(const int* __restrict__ ei, int e) {
    int i = blockIdx.x * blockDim.x + threadIdx.x;
    if (i < e) {
        int src = ei[i];
        int dst = ei[e + i];
        int pos = atomicAdd(&g_cursor[dst], 1);
        g_col[pos] = src;
    }
}

// ---------------- tiled SGEMM:  C[r,:] = (A@B)[r,:] * rowscale[r] ----------------
// BM=128, BN=64, BK=16, TM=8, TN=4, 256 threads. N,K multiples of {64,16}.
__global__ __launch_bounds__(256)
void k_sgemm(int M, int N, int K,
             const float* __restrict__ A, const float* __restrict__ B,
             float* __restrict__ C, const float* __restrict__ rowscale)
{
    const int BM = 128, BN = 64, BK = 16, TM = 8, TN = 4;
    __shared__ float As[BK][BM];
    __shared__ float Bs[BK][BN];

    int tid = threadIdx.x;
    int rowBase = blockIdx.y * BM;
    int colBase = blockIdx.x * BN;

    int tr = (tid >> 4) * TM;     // 0..120
    int tc = (tid & 15) * TN;     // 0..60

    float acc[TM][TN];
    #pragma unroll
    for (int i = 0; i < TM; i++)
        #pragma unroll
        for (int j = 0; j < TN; j++) acc[i][j] = 0.f;

    for (int k0 = 0; k0 < K; k0 += BK) {
        // A tile: BM x BK = 2048 floats = 512 float4; 2 per thread
        #pragma unroll
        for (int it = 0; it < 2; it++) {
            int idx = tid + it * 256;
            int ar  = idx >> 2;
            int ak  = (idx & 3) * 4;
            int gr  = rowBase + ar;
            float4 v = make_float4(0.f, 0.f, 0.f, 0.f);
            if (gr < M)
                v = *reinterpret_cast<const float4*>(A + (size_t)gr * K + k0 + ak);
            As[ak + 0][ar] = v.x;
            As[ak + 1][ar] = v.y;
            As[ak + 2][ar] = v.z;
            As[ak + 3][ar] = v.w;
        }
        // B tile: BK x BN = 1024 floats = 256 float4; 1 per thread
        {
            int br = tid >> 4;
            int bc = (tid & 15) * 4;
            float4 v = *reinterpret_cast<const float4*>(B + (size_t)(k0 + br) * N + colBase + bc);
            Bs[br][bc + 0] = v.x;
            Bs[br][bc + 1] = v.y;
            Bs[br][bc + 2] = v.z;
            Bs[br][bc + 3] = v.w;
        }
        __syncthreads();

        #pragma unroll
        for (int k = 0; k < BK; k++) {
            float a[TM], b[TN];
            #pragma unroll
            for (int i = 0; i < TM; i++) a[i] = As[k][tr + i];
            #pragma unroll
            for (int j = 0; j < TN; j++) b[j] = Bs[k][tc + j];
            #pragma unroll
            for (int i = 0; i < TM; i++)
                #pragma unroll
                for (int j = 0; j < TN; j++) acc[i][j] += a[i] * b[j];
        }
        __syncthreads();
    }

    #pragma unroll
    for (int i = 0; i < TM; i++) {
        int r = rowBase + tr + i;
        if (r < M) {
            float sc = rowscale ? rowscale[r] : 1.f;
            float4 o = make_float4(acc[i][0] * sc, acc[i][1] * sc,
                                   acc[i][2] * sc, acc[i][3] * sc);
            *reinterpret_cast<float4*>(C + (size_t)r * N + colBase + tc) = o;
        }
    }
}

// ---------------- pull aggregation: one block per node ----------------
// z[d, t] = act( dinv[d] * (h[d,t] + sum_{src->d} h[src,t]) + bias[t] )
__global__ void k_agg(const float* __restrict__ h, const float* __restrict__ bias,
                      float* __restrict__ z, int C, int do_relu)
{
    int node = blockIdx.x;
    int t = threadIdx.x;
    int beg = g_offsets[node];
    int end = g_offsets[node + 1];
    float acc = h[(size_t)node * C + t];     // self loop term
    for (int e = beg; e < end; e++) {
        int s = g_col[e];
        acc += h[(size_t)s * C + t];
    }
    float v = g_dinv[node] * acc + bias[t];
    if (do_relu) v = fmaxf(v, 0.f);
    z[(size_t)node * C + t] = v;
}

// ---------------- decode: dot(z2[es], z2[ed]) over 64 dims ----------------
__global__ void k_decode(const int* __restrict__ eli, float* __restrict__ out, int l)
{
    int i = blockIdx.x * blockDim.x + threadIdx.x;
    if (i >= l) return;
    int es = eli[i];
    int ed = eli[l + i];
    const float4* a = reinterpret_cast<const float4*>(g_z2 + (size_t)es * COUT);
    const float4* b = reinterpret_cast<const float4*>(g_z2 + (size_t)ed * COUT);
    float s = 0.f;
    #pragma unroll
    for (int k = 0; k < COUT / 4; k++) {
        float4 va = a[k], vb = b[k];
        s += va.x * vb.x + va.y * vb.y + va.z * vb.z + va.w * vb.w;
    }
    out[i] = s;
}

extern "C" void kernel_launch(void* const* d_in, const int* in_sizes, int n_in,
                              void* d_out, int out_size)
{
    const float* x   = (const float*)d_in[0];
    const int*   ei  = (const int*)d_in[1];    // int32 [2, E] (JAX x64 disabled)
    const int*   eli = (const int*)d_in[2];    // int32 [2, L]
    const float* W1  = (const float*)d_in[3];
    const float* b1  = (const float*)d_in[4];
    const float* W2  = (const float*)d_in[5];
    const float* b2  = (const float*)d_in[6];
    float*       out = (float*)d_out;

    int n = in_sizes[0] / CIN;   // 50000
    int e = in_sizes[1] / 2;     // 800000
    int l = in_sizes[2] / 2;     // 100000

    // resolve device-global scratch addresses (host API, capture-safe)
    float *p_h1, *p_z1, *p_h2, *p_z2, *p_dinv;
    {
        void* p;
        cudaGetSymbolAddress(&p, g_h1);   p_h1   = (float*)p;
        cudaGetSymbolAddress(&p, g_z1);   p_z1   = (float*)p;
        cudaGetSymbolAddress(&p, g_h2);   p_h2   = (float*)p;
        cudaGetSymbolAddress(&p, g_z2);   p_z2   = (float*)p;
        cudaGetSymbolAddress(&p, g_dinv); p_dinv = (float*)p;
    }

    // 1) graph preprocessing: degree, dinv, CSR(dst)
    k_zero_cnt<<<(n + 255) / 256, 256>>>(n);
    k_count<<<(e + 255) / 256, 256>>>(ei, e);
    k_dinv<<<(n + 255) / 256, 256>>>(n);
    k_scan<<<1, 1024>>>(n, e);
    k_fill<<<(e + 255) / 256, 256>>>(ei, e);

    // 2) layer 1: g1 = (x @ W1) * dinv ; z1 = relu(dinv*(g1[d]+sum g1[src]) + b1)
    {
        dim3 grid(CHID / 64, (n + 127) / 128);
        k_sgemm<<<grid, 256>>>(n, CHID, CIN, x, W1, p_h1, p_dinv);
    }
    k_agg<<<n, CHID>>>(p_h1, b1, p_z1, CHID, 1);

    // 3) layer 2: g2 = (z1 @ W2) * dinv ; z2 = dinv*(g2[d]+sum g2[src]) + b2
    {
        dim3 grid(COUT / 64, (n + 127) / 128);
        k_sgemm<<<grid, 256>>>(n, COUT, CHID, p_z1, W2, p_h2, p_dinv);
    }
    k_agg<<<n, COUT>>>(p_h2, b2, p_z2, COUT, 0);

    // 4) decode
    k_decode<<<(l + 255) / 256, 256>>>(eli, out, l);
}

// round 5
// speedup vs baseline: 1.0740x; 1.0740x over previous
#include <cuda_runtime.h>
#include <cuda_bf16.h>

// Problem constants (fixed by dataset)
#define NMAX 50000
#define EMAX 800000
#define CIN  512
#define CHID 128
#define COUT 64

// scan geometry
#define SCAN_T 256
#define SCAN_I 16
#define SCAN_CHUNK (SCAN_T*SCAN_I)                         // 4096
#define SCAN_NB ((NMAX + SCAN_CHUNK - 1)/SCAN_CHUNK)       // 13

// ---------------- device scratch (static, allocation-free) ----------------
__device__ int   g_cnt[NMAX];        // in-degree (excl self loop)
__device__ int   g_offsets[NMAX+1];  // CSR offsets by dst
__device__ int   g_cursor[NMAX];     // fill cursors
__device__ int   g_col[EMAX];        // src node per edge, grouped by dst
__device__ float g_dinv[NMAX];       // deg^-1/2 (deg includes self loop)
__device__ int   g_bsum[SCAN_NB];
__device__ int   g_bpre[SCAN_NB];
__device__ float g_h1[NMAX*CHID];    // (x@W1)*dinv[row]
__device__ float g_z1[NMAX*CHID];    // relu(agg + b1)
__device__ float g_h2[NMAX*COUT];    // (z1@W2)*dinv[row]
__device__ float g_z2[NMAX*COUT];    // agg + b2

// ---------------- graph preprocessing ----------------
__global__ void k_zero_cnt(int n) {
    int i = blockIdx.x * blockDim.x + threadIdx.x;
    if (i < n) g_cnt[i] = 0;
}

__global__ void k_count(const int* __restrict__ ei, int e) {
    int i = blockIdx.x * blockDim.x + threadIdx.x;
    if (i < e) atomicAdd(&g_cnt[ei[e + i]], 1);   // dst row
}

// per-block sums of g_cnt; fused dinv computation
__global__ void k_blocksum(int n) {
    __shared__ int sd[SCAN_T];
    int b = blockIdx.x, t = threadIdx.x;
    int base = b * SCAN_CHUNK + t * SCAN_I;
    int s = 0;
    #pragma unroll
    for (int i = 0; i < SCAN_I; i++) {
        int idx = base + i;
        if (idx < n) {
            int c = g_cnt[idx];
            s += c;
            g_dinv[idx] = rsqrtf((float)(c + 1));   // +1 self loop
        }
    }
    sd[t] = s;
    __syncthreads();
    #pragma unroll
    for (int off = SCAN_T / 2; off > 0; off >>= 1) {
        if (t < off) sd[t] += sd[t + off];
        __syncthreads();
    }
    if (t == 0) g_bsum[b] = sd[0];
}

// tiny serial scan of SCAN_NB block sums
__global__ void k_scanb() {
    if (threadIdx.x == 0) {
        int run = 0;
        for (int i = 0; i < SCAN_NB; i++) { g_bpre[i] = run; run += g_bsum[i]; }
    }
}

// per-block rescan + scatter offsets/cursors; last thread writes total
__global__ void k_scatter(int n) {
    __shared__ int sd[SCAN_T];
    int b = blockIdx.x, t = threadIdx.x;
    int base = b * SCAN_CHUNK + t * SCAN_I;
    int loc[SCAN_I];
    int s = 0;
    #pragma unroll
    for (int i = 0; i < SCAN_I; i++) {
        int idx = base + i;
        int c = (idx < n) ? g_cnt[idx] : 0;
        loc[i] = s;
        s += c;
    }
    sd[t] = s;
    __syncthreads();
    int v = s;
    for (int off = 1; off < SCAN_T; off <<= 1) {
        int u = (t >= off) ? sd[t - off] : 0;
        __syncthreads();
        sd[t] += u;
        __syncthreads();
    }
    int pre = sd[t] - v + g_bpre[b];   // exclusive prefix for this thread's first item
    #pragma unroll
    for (int i = 0; i < SCAN_I; i++) {
        int idx = base + i;
        if (idx < n) {
            int o = pre + loc[i];
            g_offsets[idx] = o;
            g_cursor[idx]  = o;
        }
    }
    if (b == gridDim.x - 1 && t == SCAN_T - 1) g_offsets[n] = pre + s;
}

__global__ void k_fill(const int* __restrict__ ei, int e) {
    int i = blockIdx.x * blockDim.x + threadIdx.x;
    if (i < e) {
        int src = ei[i];
        int dst = ei[e + i];
        int pos = atomicAdd(&g_cursor[dst], 1);
        g_col[pos] = src;
    }
}

// ---------------- tiled SGEMM:  C[r,:] = (A@B)[r,:] * rowscale[r] ----------------
// One block column covers the whole N (BN == matrix width). BM=128, BK=16,
// TM=8, TN=BN/16, 256 threads. Register prefetch of next K-slab.
template<int BN>
__global__ __launch_bounds__(256)
void k_sgemm(int M, int K,
             const float* __restrict__ A, const float* __restrict__ B,
             float* __restrict__ C, const float* __restrict__ rowscale)
{
    const int BM = 128, BK = 16, TM = 8, TN = BN / 16;
    const int A4 = BM * BK / 4;            // float4 count in A tile = 512
    const int ALD = A4 / 256;              // 2 A float4 loads per thread
    const int B4 = BK * BN / 4;            // float4 count in B tile
    const int BLD = B4 / 256;              // 1 or 2 per thread

    __shared__ float As[BK][BM];
    __shared__ float Bs[BK][BN];

    int tid = threadIdx.x;
    int rowBase = blockIdx.x * BM;

    int tr = (tid >> 4) * TM;              // 0..120
    int tc = (tid & 15) * TN;

    float acc[TM][TN];
    #pragma unroll
    for (int i = 0; i < TM; i++)
        #pragma unroll
        for (int j = 0; j < TN; j++) acc[i][j] = 0.f;

    // A-tile load indices (fixed per thread)
    int a_r[ALD], a_k[ALD];
    #pragma unroll
    for (int it = 0; it < ALD; it++) {
        int idx = tid + it * 256;
        a_r[it] = idx >> 2;                // 0..127
        a_k[it] = (idx & 3) * 4;           // 0,4,8,12
    }
    // B-tile load indices
    int b_r[BLD], b_c[BLD];
    #pragma unroll
    for (int it = 0; it < BLD; it++) {
        int idx = tid + it * 256;
        b_r[it] = idx / (BN / 4);
        b_c[it] = (idx % (BN / 4)) * 4;
    }

    // initial tile load (k0 = 0)
    #pragma unroll
    for (int it = 0; it < ALD; it++) {
        int gr = rowBase + a_r[it];
        float4 v = make_float4(0.f, 0.f, 0.f, 0.f);
        if (gr < M) v = *reinterpret_cast<const float4*>(A + (size_t)gr * K + a_k[it]);
        As[a_k[it] + 0][a_r[it]] = v.x;
        As[a_k[it] + 1][a_r[it]] = v.y;
        As[a_k[it] + 2][a_r[it]] = v.z;
        As[a_k[it] + 3][a_r[it]] = v.w;
    }
    #pragma unroll
    for (int it = 0; it < BLD; it++) {
        float4 v = *reinterpret_cast<const float4*>(B + (size_t)b_r[it] * BN + b_c[it]);
        Bs[b_r[it]][b_c[it] + 0] = v.x;
        Bs[b_r[it]][b_c[it] + 1] = v.y;
        Bs[b_r[it]][b_c[it] + 2] = v.z;
        Bs[b_r[it]][b_c[it] + 3] = v.w;
    }
    __syncthreads();

    for (int k0 = 0; k0 < K; k0 += BK) {
        // prefetch next slab into registers (overlaps with compute)
        float4 pA[ALD], pB[BLD];
        bool has_next = (k0 + BK < K);
        if (has_next) {
            #pragma unroll
            for (int it = 0; it < ALD; it++) {
                int gr = rowBase + a_r[it];
                pA[it] = make_float4(0.f, 0.f, 0.f, 0.f);
                if (gr < M)
                    pA[it] = *reinterpret_cast<const float4*>(A + (size_t)gr * K + k0 + BK + a_k[it]);
            }
            #pragma unroll
            for (int it = 0; it < BLD; it++)
                pB[it] = *reinterpret_cast<const float4*>(B + (size_t)(k0 + BK + b_r[it]) * BN + b_c[it]);
        }

        #pragma unroll
        for (int k = 0; k < BK; k++) {
            float a[TM], b[TN];
            *reinterpret_cast<float4*>(&a[0]) = *reinterpret_cast<const float4*>(&As[k][tr]);
            *reinterpret_cast<float4*>(&a[4]) = *reinterpret_cast<const float4*>(&As[k][tr + 4]);
            #pragma unroll
            for (int j = 0; j < TN; j += 4)
                *reinterpret_cast<float4*>(&b[j]) = *reinterpret_cast<const float4*>(&Bs[k][tc + j]);
            #pragma unroll
            for (int i = 0; i < TM; i++)
                #pragma unroll
                for (int j = 0; j < TN; j++) acc[i][j] += a[i] * b[j];
        }
        __syncthreads();

        if (has_next) {
            #pragma unroll
            for (int it = 0; it < ALD; it++) {
                As[a_k[it] + 0][a_r[it]] = pA[it].x;
                As[a_k[it] + 1][a_r[it]] = pA[it].y;
                As[a_k[it] + 2][a_r[it]] = pA[it].z;
                As[a_k[it] + 3][a_r[it]] = pA[it].w;
            }
            #pragma unroll
            for (int it = 0; it < BLD; it++) {
                Bs[b_r[it]][b_c[it] + 0] = pB[it].x;
                Bs[b_r[it]][b_c[it] + 1] = pB[it].y;
                Bs[b_r[it]][b_c[it] + 2] = pB[it].z;
                Bs[b_r[it]][b_c[it] + 3] = pB[it].w;
            }
            __syncthreads();
        }
    }

    #pragma unroll
    for (int i = 0; i < TM; i++) {
        int r = rowBase + tr + i;
        if (r < M) {
            float sc = rowscale[r];
            #pragma unroll
            for (int j = 0; j < TN; j += 4) {
                float4 o = make_float4(acc[i][j] * sc, acc[i][j+1] * sc,
                                       acc[i][j+2] * sc, acc[i][j+3] * sc);
                *reinterpret_cast<float4*>(C + (size_t)r * BN + tc + j) = o;
            }
        }
    }
}

// ---------------- pull aggregation: one block per node ----------------
// z[d, t] = act( dinv[d] * (h[d,t] + sum_{src->d} h[src,t]) + bias[t] )
__global__ void k_agg(const float* __restrict__ h, const float* __restrict__ bias,
                      float* __restrict__ z, int C, int do_relu)
{
    int node = blockIdx.x;
    int t = threadIdx.x;
    int beg = g_offsets[node];
    int end = g_offsets[node + 1];
    float acc = h[(size_t)node * C + t];     // self loop term
    for (int e = beg; e < end; e++) {
        int s = g_col[e];
        acc += __ldg(h + (size_t)s * C + t);
    }
    float v = g_dinv[node] * acc + bias[t];
    if (do_relu) v = fmaxf(v, 0.f);
    z[(size_t)node * C + t] = v;
}

// ---------------- decode: dot(z2[es], z2[ed]) over 64 dims ----------------
__global__ void k_decode(const int* __restrict__ eli, float* __restrict__ out, int l)
{
    int i = blockIdx.x * blockDim.x + threadIdx.x;
    if (i >= l) return;
    int es = eli[i];
    int ed = eli[l + i];
    const float4* a = reinterpret_cast<const float4*>(g_z2 + (size_t)es * COUT);
    const float4* b = reinterpret_cast<const float4*>(g_z2 + (size_t)ed * COUT);
    float s = 0.f;
    #pragma unroll
    for (int k = 0; k < COUT / 4; k++) {
        float4 va = a[k], vb = b[k];
        s += va.x * vb.x + va.y * vb.y + va.z * vb.z + va.w * vb.w;
    }
    out[i] = s;
}

extern "C" void kernel_launch(void* const* d_in, const int* in_sizes, int n_in,
                              void* d_out, int out_size)
{
    const float* x   = (const float*)d_in[0];
    const int*   ei  = (const int*)d_in[1];    // int32 [2, E]
    const int*   eli = (const int*)d_in[2];    // int32 [2, L]
    const float* W1  = (const float*)d_in[3];
    const float* b1  = (const float*)d_in[4];
    const float* W2  = (const float*)d_in[5];
    const float* b2  = (const float*)d_in[6];
    float*       out = (float*)d_out;

    int n = in_sizes[0] / CIN;   // 50000
    int e = in_sizes[1] / 2;     // 800000
    int l = in_sizes[2] / 2;     // 100000

    // resolve device-global scratch addresses (host API, capture-safe)
    float *p_h1, *p_z1, *p_h2, *p_z2, *p_dinv;
    {
        void* p;
        cudaGetSymbolAddress(&p, g_h1);   p_h1   = (float*)p;
        cudaGetSymbolAddress(&p, g_z1);   p_z1   = (float*)p;
        cudaGetSymbolAddress(&p, g_h2);   p_h2   = (float*)p;
        cudaGetSymbolAddress(&p, g_z2);   p_z2   = (float*)p;
        cudaGetSymbolAddress(&p, g_dinv); p_dinv = (float*)p;
    }

    // 1) graph preprocessing: degree, dinv, CSR(dst)
    k_zero_cnt<<<(n + 255) / 256, 256>>>(n);
    k_count<<<(e + 255) / 256, 256>>>(ei, e);
    int nb = (n + SCAN_CHUNK - 1) / SCAN_CHUNK;   // = SCAN_NB
    k_blocksum<<<nb, SCAN_T>>>(n);
    k_scanb<<<1, 32>>>();
    k_scatter<<<nb, SCAN_T>>>(n);
    k_fill<<<(e + 255) / 256, 256>>>(ei, e);

    // 2) layer 1: g1 = (x @ W1) * dinv ; z1 = relu(dinv*(g1[d]+sum g1[src]) + b1)
    k_sgemm<CHID><<<(n + 127) / 128, 256>>>(n, CIN, x, W1, p_h1, p_dinv);
    k_agg<<<n, CHID>>>(p_h1, b1, p_z1, CHID, 1);

    // 3) layer 2: g2 = (z1 @ W2) * dinv ; z2 = dinv*(g2[d]+sum g2[src]) + b2
    k_sgemm<COUT><<<(n + 127) / 128, 256>>>(n, CHID, p_z1, W2, p_h2, p_dinv);
    k_agg<<<n, COUT>>>(p_h2, b2, p_z2, COUT, 0);

    // 4) decode
    k_decode<<<(l + 255) / 256, 256>>>(eli, out, l);
}

// round 7
// speedup vs baseline: 1.7256x; 1.6067x over previous
#include <cuda_runtime.h>
#include <cuda_bf16.h>
#include <cstdint>

// Problem constants (fixed by dataset)
#define NMAX 50000
#define EMAX 800000
#define CIN  512
#define CHID 128
#define COUT 64

// scan geometry
#define SCAN_T 256
#define SCAN_I 16
#define SCAN_CHUNK (SCAN_T*SCAN_I)                         // 4096
#define SCAN_NB ((NMAX + SCAN_CHUNK - 1)/SCAN_CHUNK)       // 13

// ---------------- device scratch (static, allocation-free) ----------------
__device__ int   g_cnt[NMAX];
__device__ int   g_offsets[NMAX+1];
__device__ int   g_cursor[NMAX];
__device__ int   g_col[EMAX];
__device__ float g_dinv[NMAX];
__device__ int   g_bsum[SCAN_NB];
__device__ int   g_bpre[SCAN_NB];
__device__ float g_h1[NMAX*CHID];
__device__ float g_z1[NMAX*CHID];
__device__ float g_h2[NMAX*COUT];
__device__ float g_z2[NMAX*COUT];
// weights transposed to [N][K], split into bf16 hi/lo
__device__ __nv_bfloat16 g_w1hi[CHID*CIN];
__device__ __nv_bfloat16 g_w1lo[CHID*CIN];
__device__ __nv_bfloat16 g_w2hi[COUT*CHID];
__device__ __nv_bfloat16 g_w2lo[COUT*CHID];

// ---------------- graph preprocessing ----------------
__global__ void k_zero_cnt(int n) {
    int i = blockIdx.x * blockDim.x + threadIdx.x;
    if (i < n) g_cnt[i] = 0;
}

__global__ void k_count(const int* __restrict__ ei, int e) {
    int i = blockIdx.x * blockDim.x + threadIdx.x;
    if (i < e) atomicAdd(&g_cnt[ei[e + i]], 1);
}

__global__ void k_blocksum(int n) {
    __shared__ int sd[SCAN_T];
    int b = blockIdx.x, t = threadIdx.x;
    int base = b * SCAN_CHUNK + t * SCAN_I;
    int s = 0;
    #pragma unroll
    for (int i = 0; i < SCAN_I; i++) {
        int idx = base + i;
        if (idx < n) {
            int c = g_cnt[idx];
            s += c;
            g_dinv[idx] = rsqrtf((float)(c + 1));
        }
    }
    sd[t] = s;
    __syncthreads();
    #pragma unroll
    for (int off = SCAN_T / 2; off > 0; off >>= 1) {
        if (t < off) sd[t] += sd[t + off];
        __syncthreads();
    }
    if (t == 0) g_bsum[b] = sd[0];
}

__global__ void k_scanb() {
    if (threadIdx.x == 0) {
        int run = 0;
        for (int i = 0; i < SCAN_NB; i++) { g_bpre[i] = run; run += g_bsum[i]; }
    }
}

__global__ void k_scatter(int n) {
    __shared__ int sd[SCAN_T];
    int b = blockIdx.x, t = threadIdx.x;
    int base = b * SCAN_CHUNK + t * SCAN_I;
    int loc[SCAN_I];
    int s = 0;
    #pragma unroll
    for (int i = 0; i < SCAN_I; i++) {
        int idx = base + i;
        int c = (idx < n) ? g_cnt[idx] : 0;
        loc[i] = s;
        s += c;
    }
    sd[t] = s;
    __syncthreads();
    int v = s;
    for (int off = 1; off < SCAN_T; off <<= 1) {
        int u = (t >= off) ? sd[t - off] : 0;
        __syncthreads();
        sd[t] += u;
        __syncthreads();
    }
    int pre = sd[t] - v + g_bpre[b];
    #pragma unroll
    for (int i = 0; i < SCAN_I; i++) {
        int idx = base + i;
        if (idx < n) {
            int o = pre + loc[i];
            g_offsets[idx] = o;
            g_cursor[idx]  = o;
        }
    }
    if (b == gridDim.x - 1 && t == SCAN_T - 1) g_offsets[n] = pre + s;
}

__global__ void k_fill(const int* __restrict__ ei, int e) {
    int i = blockIdx.x * blockDim.x + threadIdx.x;
    if (i < e) {
        int src = ei[i];
        int dst = ei[e + i];
        int pos = atomicAdd(&g_cursor[dst], 1);
        g_col[pos] = src;
    }
}

// ---------------- weight prep: transpose + hi/lo bf16 split ----------------
// W: [K][N] fp32 -> Whi/Wlo: [N][K] bf16
__global__ void k_prep_w(const float* __restrict__ W,
                         __nv_bfloat16* __restrict__ Whi,
                         __nv_bfloat16* __restrict__ Wlo, int K, int N)
{
    int i = blockIdx.x * blockDim.x + threadIdx.x;
    if (i < K * N) {
        int k = i / N, nn = i % N;
        float w = W[i];
        __nv_bfloat16 hi = __float2bfloat16(w);
        float lo = w - __bfloat162float(hi);
        Whi[(size_t)nn * K + k] = hi;
        Wlo[(size_t)nn * K + k] = __float2bfloat16(lo);
    }
}

// ---------------- mma helpers ----------------
__device__ __forceinline__ uint32_t smem_u32(const void* p) {
    uint32_t a;
    asm("{ .reg .u64 t; cvta.to.shared.u64 t, %1; cvt.u32.u64 %0, t; }" : "=r"(a) : "l"(p));
    return a;
}
__device__ __forceinline__ void ldm_x4(uint32_t* r, uint32_t addr) {
    asm volatile("ldmatrix.sync.aligned.m8n8.x4.shared.b16 {%0,%1,%2,%3}, [%4];"
                 : "=r"(r[0]), "=r"(r[1]), "=r"(r[2]), "=r"(r[3]) : "r"(addr));
}
__device__ __forceinline__ void mma_bf16(float* d, const uint32_t* a, const uint32_t* b) {
    asm volatile(
        "mma.sync.aligned.m16n8k16.row.col.f32.bf16.bf16.f32 "
        "{%0,%1,%2,%3}, {%4,%5,%6,%7}, {%8,%9}, {%0,%1,%2,%3};"
        : "+f"(d[0]), "+f"(d[1]), "+f"(d[2]), "+f"(d[3])
        : "r"(a[0]), "r"(a[1]), "r"(a[2]), "r"(a[3]), "r"(b[0]), "r"(b[1]));
}
__device__ __forceinline__ void split1(float a, __nv_bfloat16& hi, __nv_bfloat16& lo) {
    hi = __float2bfloat16(a);
    lo = __float2bfloat16(a - __bfloat162float(hi));
}

// ---------------- split-precision bf16 tensor-core GEMM ----------------
// C[r, 0:BN] = (A @ W)[r, :] * dinv[r]
// A: [M, K] fp32; Bhi/Blo: [BN][K] bf16 (W^T, K-major).
// 256 threads, BM=128, BK=16, warp grid 2(m) x 4(n), warp tile 64 x (BN/4).
template<int BN, int K>
__global__ __launch_bounds__(256)
void k_mma(int M, const float* __restrict__ A,
           const __nv_bfloat16* __restrict__ Bhi,
           const __nv_bfloat16* __restrict__ Blo,
           float* __restrict__ C, const float* __restrict__ dinv)
{
    const int BM = 128, BK = 16;
    const int LDA = 24, LDB = 24;        // padded halfs per row (48B: 16B-aligned, conflict-free)
    const int WTN = BN / 4;              // 32 or 16
    const int NT  = WTN / 8;             // 4 or 2

    __shared__ __nv_bfloat16 sAh[BM][LDA], sAl[BM][LDA];
    __shared__ __nv_bfloat16 sBh[BN][LDB], sBl[BN][LDB];

    int tid = threadIdx.x, wid = tid >> 5, lane = tid & 31;
    int wm = wid >> 2;                   // 0..1
    int wn = wid & 3;                    // 0..3
    int rowBase = blockIdx.x * BM;

    float acc[4][NT][4];
    #pragma unroll
    for (int mi = 0; mi < 4; mi++)
        #pragma unroll
        for (int ni = 0; ni < NT; ni++)
            #pragma unroll
            for (int q = 0; q < 4; q++) acc[mi][ni][q] = 0.f;

    // global A load mapping: 512 float4/iter, 2 per thread
    int ar0 = tid >> 2;                  // 0..63
    int akq = (tid & 3) * 4;             // 0,4,8,12
    // global B load mapping: BN*2 uint4/iter
    int bn  = tid >> 1;                  // 0..127
    int bkq = (tid & 1) * 8;             // 0,8
    bool bvalid = (tid < BN * 2);

    float4 fa[2];
    uint4  fbh, fbl;

    // preload k0 = 0
    {
        #pragma unroll
        for (int it = 0; it < 2; it++) {
            int gr = rowBase + ar0 + it * 64;
            fa[it] = make_float4(0.f, 0.f, 0.f, 0.f);
            if (gr < M) fa[it] = *reinterpret_cast<const float4*>(A + (size_t)gr * K + akq);
        }
        if (bvalid) {
            fbh = *reinterpret_cast<const uint4*>(Bhi + (size_t)bn * K + bkq);
            fbl = *reinterpret_cast<const uint4*>(Blo + (size_t)bn * K + bkq);
        }
    }

    uint32_t sAh_base = smem_u32(&sAh[0][0]);
    uint32_t sAl_base = smem_u32(&sAl[0][0]);

    for (int k0 = 0; k0 < K; k0 += BK) {
        // store prefetched regs to SMEM (split A on the fly)
        #pragma unroll
        for (int it = 0; it < 2; it++) {
            int r = ar0 + it * 64;
            __nv_bfloat16 h[4], l[4];
            split1(fa[it].x, h[0], l[0]);
            split1(fa[it].y, h[1], l[1]);
            split1(fa[it].z, h[2], l[2]);
            split1(fa[it].w, h[3], l[3]);
            *reinterpret_cast<uint2*>(&sAh[r][akq]) = *reinterpret_cast<uint2*>(h);
            *reinterpret_cast<uint2*>(&sAl[r][akq]) = *reinterpret_cast<uint2*>(l);
        }
        if (bvalid) {
            *reinterpret_cast<uint4*>(&sBh[bn][bkq]) = fbh;
            *reinterpret_cast<uint4*>(&sBl[bn][bkq]) = fbl;
        }
        __syncthreads();

        // prefetch next slab
        if (k0 + BK < K) {
            #pragma unroll
            for (int it = 0; it < 2; it++) {
                int gr = rowBase + ar0 + it * 64;
                fa[it] = make_float4(0.f, 0.f, 0.f, 0.f);
                if (gr < M)
                    fa[it] = *reinterpret_cast<const float4*>(A + (size_t)gr * K + k0 + BK + akq);
            }
            if (bvalid) {
                fbh = *reinterpret_cast<const uint4*>(Bhi + (size_t)bn * K + k0 + BK + bkq);
                fbl = *reinterpret_cast<const uint4*>(Blo + (size_t)bn * K + k0 + BK + bkq);
            }
        }

        // A fragments via ldmatrix.x4 (conflict-free with 48B stride)
        uint32_t ah[4][4], al[4][4];
        int arow = wm * 64 + (lane & 15);
        int acol = (lane >> 4) * 8;
        #pragma unroll
        for (int mi = 0; mi < 4; mi++) {
            uint32_t off = (uint32_t)((arow + mi * 16) * LDA + acol) * 2;
            ldm_x4(ah[mi], sAh_base + off);
            ldm_x4(al[mi], sAl_base + off);
        }
        // B fragments via direct b32 LDS
        uint32_t bh[NT][2], bl[NT][2];
        int bn0 = wn * WTN + (lane >> 2);
        int bk  = (lane & 3) * 2;
        #pragma unroll
        for (int ni = 0; ni < NT; ni++) {
            bh[ni][0] = *reinterpret_cast<const uint32_t*>(&sBh[bn0 + ni * 8][bk]);
            bh[ni][1] = *reinterpret_cast<const uint32_t*>(&sBh[bn0 + ni * 8][bk + 8]);
            bl[ni][0] = *reinterpret_cast<const uint32_t*>(&sBl[bn0 + ni * 8][bk]);
            bl[ni][1] = *reinterpret_cast<const uint32_t*>(&sBl[bn0 + ni * 8][bk + 8]);
        }

        #pragma unroll
        for (int mi = 0; mi < 4; mi++)
            #pragma unroll
            for (int ni = 0; ni < NT; ni++) {
                mma_bf16(acc[mi][ni], ah[mi], bh[ni]);
                mma_bf16(acc[mi][ni], al[mi], bh[ni]);
                mma_bf16(acc[mi][ni], ah[mi], bl[ni]);
            }
        __syncthreads();
    }

    // epilogue: scale by dinv[row], store fp32
    #pragma unroll
    for (int mi = 0; mi < 4; mi++) {
        int r = rowBase + wm * 64 + mi * 16 + (lane >> 2);
        #pragma unroll
        for (int ni = 0; ni < NT; ni++) {
            int cn = wn * WTN + ni * 8 + (lane & 3) * 2;
            if (r < M) {
                float sc = dinv[r];
                float2 o = make_float2(acc[mi][ni][0] * sc, acc[mi][ni][1] * sc);
                *reinterpret_cast<float2*>(C + (size_t)r * BN + cn) = o;
            }
            if (r + 8 < M) {
                float sc = dinv[r + 8];
                float2 o = make_float2(acc[mi][ni][2] * sc, acc[mi][ni][3] * sc);
                *reinterpret_cast<float2*>(C + (size_t)(r + 8) * BN + cn) = o;
            }
        }
    }
}

// ---------------- pull aggregation: one block per node ----------------
__global__ void k_agg(const float* __restrict__ h, const float* __restrict__ bias,
                      float* __restrict__ z, int C, int do_relu)
{
    int node = blockIdx.x;
    int t = threadIdx.x;
    int beg = g_offsets[node];
    int end = g_offsets[node + 1];
    float acc = h[(size_t)node * C + t];
    for (int e = beg; e < end; e++) {
        int s = g_col[e];
        acc += __ldg(h + (size_t)s * C + t);
    }
    float v = g_dinv[node] * acc + bias[t];
    if (do_relu) v = fmaxf(v, 0.f);
    z[(size_t)node * C + t] = v;
}

// ---------------- decode ----------------
__global__ void k_decode(const int* __restrict__ eli, float* __restrict__ out, int l)
{
    int i = blockIdx.x * blockDim.x + threadIdx.x;
    if (i >= l) return;
    int es = eli[i];
    int ed = eli[l + i];
    const float4* a = reinterpret_cast<const float4*>(g_z2 + (size_t)es * COUT);
    const float4* b = reinterpret_cast<const float4*>(g_z2 + (size_t)ed * COUT);
    float s = 0.f;
    #pragma unroll
    for (int k = 0; k < COUT / 4; k++) {
        float4 va = a[k], vb = b[k];
        s += va.x * vb.x + va.y * vb.y + va.z * vb.z + va.w * vb.w;
    }
    out[i] = s;
}

extern "C" void kernel_launch(void* const* d_in, const int* in_sizes, int n_in,
                              void* d_out, int out_size)
{
    const float* x   = (const float*)d_in[0];
    const int*   ei  = (const int*)d_in[1];
    const int*   eli = (const int*)d_in[2];
    const float* W1  = (const float*)d_in[3];
    const float* b1  = (const float*)d_in[4];
    const float* W2  = (const float*)d_in[5];
    const float* b2  = (const float*)d_in[6];
    float*       out = (float*)d_out;

    int n = in_sizes[0] / CIN;   // 50000
    int e = in_sizes[1] / 2;     // 800000
    int l = in_sizes[2] / 2;     // 100000

    float *p_h1, *p_z1, *p_h2, *p_z2, *p_dinv;
    __nv_bfloat16 *p_w1hi, *p_w1lo, *p_w2hi, *p_w2lo;
    {
        void* p;
        cudaGetSymbolAddress(&p, g_h1);   p_h1   = (float*)p;
        cudaGetSymbolAddress(&p, g_z1);   p_z1   = (float*)p;
        cudaGetSymbolAddress(&p, g_h2);   p_h2   = (float*)p;
        cudaGetSymbolAddress(&p, g_z2);   p_z2   = (float*)p;
        cudaGetSymbolAddress(&p, g_dinv); p_dinv = (float*)p;
        cudaGetSymbolAddress(&p, g_w1hi); p_w1hi = (__nv_bfloat16*)p;
        cudaGetSymbolAddress(&p, g_w1lo); p_w1lo = (__nv_bfloat16*)p;
        cudaGetSymbolAddress(&p, g_w2hi); p_w2hi = (__nv_bfloat16*)p;
        cudaGetSymbolAddress(&p, g_w2lo); p_w2lo = (__nv_bfloat16*)p;
    }

    // 1) graph preprocessing + weight prep
    k_zero_cnt<<<(n + 255) / 256, 256>>>(n);
    k_count<<<(e + 255) / 256, 256>>>(ei, e);
    int nb = (n + SCAN_CHUNK - 1) / SCAN_CHUNK;
    k_blocksum<<<nb, SCAN_T>>>(n);
    k_scanb<<<1, 32>>>();
    k_scatter<<<nb, SCAN_T>>>(n);
    k_fill<<<(e + 255) / 256, 256>>>(ei, e);
    k_prep_w<<<(CIN * CHID + 255) / 256, 256>>>(W1, p_w1hi, p_w1lo, CIN, CHID);
    k_prep_w<<<(CHID * COUT + 255) / 256, 256>>>(W2, p_w2hi, p_w2lo, CHID, COUT);

    // 2) layer 1: split-precision bf16 mma GEMM + aggregation
    k_mma<CHID, CIN><<<(n + 127) / 128, 256>>>(n, x, p_w1hi, p_w1lo, p_h1, p_dinv);
    k_agg<<<n, CHID>>>(p_h1, b1, p_z1, CHID, 1);

    // 3) layer 2: same kernel, smaller shapes + aggregation
    k_mma<COUT, CHID><<<(n + 127) / 128, 256>>>(n, p_z1, p_w2hi, p_w2lo, p_h2, p_dinv);
    k_agg<<<n, COUT>>>(p_h2, b2, p_z2, COUT, 0);

    // 4) decode
    k_decode<<<(l + 255) / 256, 256>>>(eli, out, l);
}

// round 8
// speedup vs baseline: 2.3376x; 1.3547x over previous
#include <cuda_runtime.h>
#include <cuda_bf16.h>
#include <cstdint>

// Problem constants (fixed by dataset)
#define NMAX 50000
#define EMAX 800000
#define CIN  512
#define CHID 128
#define COUT 64

// scan geometry
#define SCAN_T 256
#define SCAN_I 16
#define SCAN_CHUNK (SCAN_T*SCAN_I)                         // 4096
#define SCAN_NB ((NMAX + SCAN_CHUNK - 1)/SCAN_CHUNK)       // 13

// ---------------- device scratch (static, allocation-free) ----------------
__device__ int   g_cnt[NMAX];
__device__ int   g_offsets[NMAX+1];
__device__ int   g_cursor[NMAX];
__device__ int   g_col[EMAX];
__device__ float g_dinv[NMAX];
__device__ int   g_bsum[SCAN_NB];
__device__ int   g_bpre[SCAN_NB];
__device__ float g_h1[NMAX*CHID];
__device__ float g_z1[NMAX*CHID];
__device__ float g_h2[NMAX*COUT];
__device__ float g_z2[NMAX*COUT];
// weights transposed to [N][K], split into bf16 hi/lo
__device__ __nv_bfloat16 g_w1hi[CHID*CIN];
__device__ __nv_bfloat16 g_w1lo[CHID*CIN];
__device__ __nv_bfloat16 g_w2hi[COUT*CHID];
__device__ __nv_bfloat16 g_w2lo[COUT*CHID];

// ---------------- graph preprocessing ----------------
__global__ void k_zero_cnt(int n) {
    int i = blockIdx.x * blockDim.x + threadIdx.x;
    if (i < n) g_cnt[i] = 0;
}

__global__ void k_count(const int* __restrict__ ei, int e) {
    int i = blockIdx.x * blockDim.x + threadIdx.x;
    if (i < e) atomicAdd(&g_cnt[ei[e + i]], 1);
}

__global__ void k_blocksum(int n) {
    __shared__ int sd[SCAN_T];
    int b = blockIdx.x, t = threadIdx.x;
    int base = b * SCAN_CHUNK + t * SCAN_I;
    int s = 0;
    #pragma unroll
    for (int i = 0; i < SCAN_I; i++) {
        int idx = base + i;
        if (idx < n) {
            int c = g_cnt[idx];
            s += c;
            g_dinv[idx] = rsqrtf((float)(c + 1));
        }
    }
    sd[t] = s;
    __syncthreads();
    #pragma unroll
    for (int off = SCAN_T / 2; off > 0; off >>= 1) {
        if (t < off) sd[t] += sd[t + off];
        __syncthreads();
    }
    if (t == 0) g_bsum[b] = sd[0];
}

__global__ void k_scanb() {
    if (threadIdx.x == 0) {
        int run = 0;
        for (int i = 0; i < SCAN_NB; i++) { g_bpre[i] = run; run += g_bsum[i]; }
    }
}

__global__ void k_scatter(int n) {
    __shared__ int sd[SCAN_T];
    int b = blockIdx.x, t = threadIdx.x;
    int base = b * SCAN_CHUNK + t * SCAN_I;
    int loc[SCAN_I];
    int s = 0;
    #pragma unroll
    for (int i = 0; i < SCAN_I; i++) {
        int idx = base + i;
        int c = (idx < n) ? g_cnt[idx] : 0;
        loc[i] = s;
        s += c;
    }
    sd[t] = s;
    __syncthreads();
    int v = s;
    for (int off = 1; off < SCAN_T; off <<= 1) {
        int u = (t >= off) ? sd[t - off] : 0;
        __syncthreads();
        sd[t] += u;
        __syncthreads();
    }
    int pre = sd[t] - v + g_bpre[b];
    #pragma unroll
    for (int i = 0; i < SCAN_I; i++) {
        int idx = base + i;
        if (idx < n) {
            int o = pre + loc[i];
            g_offsets[idx] = o;
            g_cursor[idx]  = o;
        }
    }
    if (b == gridDim.x - 1 && t == SCAN_T - 1) g_offsets[n] = pre + s;
}

__global__ void k_fill(const int* __restrict__ ei, int e) {
    int i = blockIdx.x * blockDim.x + threadIdx.x;
    if (i < e) {
        int src = ei[i];
        int dst = ei[e + i];
        int pos = atomicAdd(&g_cursor[dst], 1);
        g_col[pos] = src;
    }
}

// ---------------- weight prep: transpose + hi/lo bf16 split ----------------
__global__ void k_prep_w(const float* __restrict__ W,
                         __nv_bfloat16* __restrict__ Whi,
                         __nv_bfloat16* __restrict__ Wlo, int K, int N)
{
    int i = blockIdx.x * blockDim.x + threadIdx.x;
    if (i < K * N) {
        int k = i / N, nn = i % N;
        float w = W[i];
        __nv_bfloat16 hi = __float2bfloat16(w);
        float lo = w - __bfloat162float(hi);
        Whi[(size_t)nn * K + k] = hi;
        Wlo[(size_t)nn * K + k] = __float2bfloat16(lo);
    }
}

// ---------------- mma helpers ----------------
__device__ __forceinline__ uint32_t smem_u32(const void* p) {
    uint32_t a;
    asm("{ .reg .u64 t; cvta.to.shared.u64 t, %1; cvt.u32.u64 %0, t; }" : "=r"(a) : "l"(p));
    return a;
}
__device__ __forceinline__ void ldm_x4(uint32_t* r, uint32_t addr) {
    asm volatile("ldmatrix.sync.aligned.m8n8.x4.shared.b16 {%0,%1,%2,%3}, [%4];"
                 : "=r"(r[0]), "=r"(r[1]), "=r"(r[2]), "=r"(r[3]) : "r"(addr));
}
__device__ __forceinline__ void mma_bf16(float* d, const uint32_t* a, const uint32_t* b) {
    asm volatile(
        "mma.sync.aligned.m16n8k16.row.col.f32.bf16.bf16.f32 "
        "{%0,%1,%2,%3}, {%4,%5,%6,%7}, {%8,%9}, {%0,%1,%2,%3};"
        : "+f"(d[0]), "+f"(d[1]), "+f"(d[2]), "+f"(d[3])
        : "r"(a[0]), "r"(a[1]), "r"(a[2]), "r"(a[3]), "r"(b[0]), "r"(b[1]));
}
__device__ __forceinline__ void split1(float a, __nv_bfloat16& hi, __nv_bfloat16& lo) {
    hi = __float2bfloat16(a);
    lo = __float2bfloat16(a - __bfloat162float(hi));
}

// ---------------- split-precision bf16 tensor-core GEMM ----------------
template<int BN, int K>
__global__ __launch_bounds__(256)
void k_mma(int M, const float* __restrict__ A,
           const __nv_bfloat16* __restrict__ Bhi,
           const __nv_bfloat16* __restrict__ Blo,
           float* __restrict__ C, const float* __restrict__ dinv)
{
    const int BM = 128, BK = 16;
    const int LDA = 24, LDB = 24;
    const int WTN = BN / 4;
    const int NT  = WTN / 8;

    __shared__ __nv_bfloat16 sAh[BM][LDA], sAl[BM][LDA];
    __shared__ __nv_bfloat16 sBh[BN][LDB], sBl[BN][LDB];

    int tid = threadIdx.x, wid = tid >> 5, lane = tid & 31;
    int wm = wid >> 2;
    int wn = wid & 3;
    int rowBase = blockIdx.x * BM;

    float acc[4][NT][4];
    #pragma unroll
    for (int mi = 0; mi < 4; mi++)
        #pragma unroll
        for (int ni = 0; ni < NT; ni++)
            #pragma unroll
            for (int q = 0; q < 4; q++) acc[mi][ni][q] = 0.f;

    int ar0 = tid >> 2;
    int akq = (tid & 3) * 4;
    int bn  = tid >> 1;
    int bkq = (tid & 1) * 8;
    bool bvalid = (tid < BN * 2);

    float4 fa[2];
    uint4  fbh, fbl;

    {
        #pragma unroll
        for (int it = 0; it < 2; it++) {
            int gr = rowBase + ar0 + it * 64;
            fa[it] = make_float4(0.f, 0.f, 0.f, 0.f);
            if (gr < M) fa[it] = *reinterpret_cast<const float4*>(A + (size_t)gr * K + akq);
        }
        if (bvalid) {
            fbh = *reinterpret_cast<const uint4*>(Bhi + (size_t)bn * K + bkq);
            fbl = *reinterpret_cast<const uint4*>(Blo + (size_t)bn * K + bkq);
        }
    }

    uint32_t sAh_base = smem_u32(&sAh[0][0]);
    uint32_t sAl_base = smem_u32(&sAl[0][0]);

    for (int k0 = 0; k0 < K; k0 += BK) {
        #pragma unroll
        for (int it = 0; it < 2; it++) {
            int r = ar0 + it * 64;
            __nv_bfloat16 h[4], l[4];
            split1(fa[it].x, h[0], l[0]);
            split1(fa[it].y, h[1], l[1]);
            split1(fa[it].z, h[2], l[2]);
            split1(fa[it].w, h[3], l[3]);
            *reinterpret_cast<uint2*>(&sAh[r][akq]) = *reinterpret_cast<uint2*>(h);
            *reinterpret_cast<uint2*>(&sAl[r][akq]) = *reinterpret_cast<uint2*>(l);
        }
        if (bvalid) {
            *reinterpret_cast<uint4*>(&sBh[bn][bkq]) = fbh;
            *reinterpret_cast<uint4*>(&sBl[bn][bkq]) = fbl;
        }
        __syncthreads();

        if (k0 + BK < K) {
            #pragma unroll
            for (int it = 0; it < 2; it++) {
                int gr = rowBase + ar0 + it * 64;
                fa[it] = make_float4(0.f, 0.f, 0.f, 0.f);
                if (gr < M)
                    fa[it] = *reinterpret_cast<const float4*>(A + (size_t)gr * K + k0 + BK + akq);
            }
            if (bvalid) {
                fbh = *reinterpret_cast<const uint4*>(Bhi + (size_t)bn * K + k0 + BK + bkq);
                fbl = *reinterpret_cast<const uint4*>(Blo + (size_t)bn * K + k0 + BK + bkq);
            }
        }

        uint32_t ah[4][4], al[4][4];
        int arow = wm * 64 + (lane & 15);
        int acol = (lane >> 4) * 8;
        #pragma unroll
        for (int mi = 0; mi < 4; mi++) {
            uint32_t off = (uint32_t)((arow + mi * 16) * LDA + acol) * 2;
            ldm_x4(ah[mi], sAh_base + off);
            ldm_x4(al[mi], sAl_base + off);
        }
        uint32_t bh[NT][2], bl[NT][2];
        int bn0 = wn * WTN + (lane >> 2);
        int bk  = (lane & 3) * 2;
        #pragma unroll
        for (int ni = 0; ni < NT; ni++) {
            bh[ni][0] = *reinterpret_cast<const uint32_t*>(&sBh[bn0 + ni * 8][bk]);
            bh[ni][1] = *reinterpret_cast<const uint32_t*>(&sBh[bn0 + ni * 8][bk + 8]);
            bl[ni][0] = *reinterpret_cast<const uint32_t*>(&sBl[bn0 + ni * 8][bk]);
            bl[ni][1] = *reinterpret_cast<const uint32_t*>(&sBl[bn0 + ni * 8][bk + 8]);
        }

        #pragma unroll
        for (int mi = 0; mi < 4; mi++)
            #pragma unroll
            for (int ni = 0; ni < NT; ni++) {
                mma_bf16(acc[mi][ni], ah[mi], bh[ni]);
                mma_bf16(acc[mi][ni], al[mi], bh[ni]);
                mma_bf16(acc[mi][ni], ah[mi], bl[ni]);
            }
        __syncthreads();
    }

    #pragma unroll
    for (int mi = 0; mi < 4; mi++) {
        int r = rowBase + wm * 64 + mi * 16 + (lane >> 2);
        #pragma unroll
        for (int ni = 0; ni < NT; ni++) {
            int cn = wn * WTN + ni * 8 + (lane & 3) * 2;
            if (r < M) {
                float sc = dinv[r];
                float2 o = make_float2(acc[mi][ni][0] * sc, acc[mi][ni][1] * sc);
                *reinterpret_cast<float2*>(C + (size_t)r * BN + cn) = o;
            }
            if (r + 8 < M) {
                float sc = dinv[r + 8];
                float2 o = make_float2(acc[mi][ni][2] * sc, acc[mi][ni][3] * sc);
                *reinterpret_cast<float2*>(C + (size_t)(r + 8) * BN + cn) = o;
            }
        }
    }
}

// ---------------- warp-per-node aggregation, float4 lanes, 4-edge unroll ----
// C=128: lane owns one float4 (32 lanes * 4 = 128 dims)
__global__ __launch_bounds__(256)
void k_agg128(const float* __restrict__ h, const float* __restrict__ bias,
              float* __restrict__ z, int n, int do_relu)
{
    int node = blockIdx.x * 8 + (threadIdx.x >> 5);
    if (node >= n) return;
    int lane = threadIdx.x & 31;
    const float4* hb = reinterpret_cast<const float4*>(h);

    int beg = g_offsets[node];
    int end = g_offsets[node + 1];
    float4 acc = hb[(size_t)node * 32 + lane];    // self loop

    int e = beg;
    for (; e + 4 <= end; e += 4) {
        int s0 = g_col[e], s1 = g_col[e+1], s2 = g_col[e+2], s3 = g_col[e+3];
        float4 v0 = hb[(size_t)s0 * 32 + lane];
        float4 v1 = hb[(size_t)s1 * 32 + lane];
        float4 v2 = hb[(size_t)s2 * 32 + lane];
        float4 v3 = hb[(size_t)s3 * 32 + lane];
        acc.x += v0.x + v1.x + v2.x + v3.x;
        acc.y += v0.y + v1.y + v2.y + v3.y;
        acc.z += v0.z + v1.z + v2.z + v3.z;
        acc.w += v0.w + v1.w + v2.w + v3.w;
    }
    for (; e < end; e++) {
        float4 v = hb[(size_t)g_col[e] * 32 + lane];
        acc.x += v.x; acc.y += v.y; acc.z += v.z; acc.w += v.w;
    }

    float di = g_dinv[node];
    float4 bb = reinterpret_cast<const float4*>(bias)[lane];
    acc.x = acc.x * di + bb.x;
    acc.y = acc.y * di + bb.y;
    acc.z = acc.z * di + bb.z;
    acc.w = acc.w * di + bb.w;
    if (do_relu) {
        acc.x = fmaxf(acc.x, 0.f); acc.y = fmaxf(acc.y, 0.f);
        acc.z = fmaxf(acc.z, 0.f); acc.w = fmaxf(acc.w, 0.f);
    }
    reinterpret_cast<float4*>(z)[(size_t)node * 32 + lane] = acc;
}

// C=64: lane owns one float2
__global__ __launch_bounds__(256)
void k_agg64(const float* __restrict__ h, const float* __restrict__ bias,
             float* __restrict__ z, int n, int do_relu)
{
    int node = blockIdx.x * 8 + (threadIdx.x >> 5);
    if (node >= n) return;
    int lane = threadIdx.x & 31;
    const float2* hb = reinterpret_cast<const float2*>(h);

    int beg = g_offsets[node];
    int end = g_offsets[node + 1];
    float2 acc = hb[(size_t)node * 32 + lane];

    int e = beg;
    for (; e + 4 <= end; e += 4) {
        int s0 = g_col[e], s1 = g_col[e+1], s2 = g_col[e+2], s3 = g_col[e+3];
        float2 v0 = hb[(size_t)s0 * 32 + lane];
        float2 v1 = hb[(size_t)s1 * 32 + lane];
        float2 v2 = hb[(size_t)s2 * 32 + lane];
        float2 v3 = hb[(size_t)s3 * 32 + lane];
        acc.x += v0.x + v1.x + v2.x + v3.x;
        acc.y += v0.y + v1.y + v2.y + v3.y;
    }
    for (; e < end; e++) {
        float2 v = hb[(size_t)g_col[e] * 32 + lane];
        acc.x += v.x; acc.y += v.y;
    }

    float di = g_dinv[node];
    float2 bb = reinterpret_cast<const float2*>(bias)[lane];
    acc.x = acc.x * di + bb.x;
    acc.y = acc.y * di + bb.y;
    if (do_relu) { acc.x = fmaxf(acc.x, 0.f); acc.y = fmaxf(acc.y, 0.f); }
    reinterpret_cast<float2*>(z)[(size_t)node * 32 + lane] = acc;
}

// ---------------- decode ----------------
__global__ void k_decode(const int* __restrict__ eli, float* __restrict__ out, int l)
{
    int i = blockIdx.x * blockDim.x + threadIdx.x;
    if (i >= l) return;
    int es = eli[i];
    int ed = eli[l + i];
    const float4* a = reinterpret_cast<const float4*>(g_z2 + (size_t)es * COUT);
    const float4* b = reinterpret_cast<const float4*>(g_z2 + (size_t)ed * COUT);
    float s = 0.f;
    #pragma unroll
    for (int k = 0; k < COUT / 4; k++) {
        float4 va = a[k], vb = b[k];
        s += va.x * vb.x + va.y * vb.y + va.z * vb.z + va.w * vb.w;
    }
    out[i] = s;
}

extern "C" void kernel_launch(void* const* d_in, const int* in_sizes, int n_in,
                              void* d_out, int out_size)
{
    const float* x   = (const float*)d_in[0];
    const int*   ei  = (const int*)d_in[1];
    const int*   eli = (const int*)d_in[2];
    const float* W1  = (const float*)d_in[3];
    const float* b1  = (const float*)d_in[4];
    const float* W2  = (const float*)d_in[5];
    const float* b2  = (const float*)d_in[6];
    float*       out = (float*)d_out;

    int n = in_sizes[0] / CIN;   // 50000
    int e = in_sizes[1] / 2;     // 800000
    int l = in_sizes[2] / 2;     // 100000

    float *p_h1, *p_z1, *p_h2, *p_z2, *p_dinv;
    __nv_bfloat16 *p_w1hi, *p_w1lo, *p_w2hi, *p_w2lo;
    {
        void* p;
        cudaGetSymbolAddress(&p, g_h1);   p_h1   = (float*)p;
        cudaGetSymbolAddress(&p, g_z1);   p_z1   = (float*)p;
        cudaGetSymbolAddress(&p, g_h2);   p_h2   = (float*)p;
        cudaGetSymbolAddress(&p, g_z2);   p_z2   = (float*)p;
        cudaGetSymbolAddress(&p, g_dinv); p_dinv = (float*)p;
        cudaGetSymbolAddress(&p, g_w1hi); p_w1hi = (__nv_bfloat16*)p;
        cudaGetSymbolAddress(&p, g_w1lo); p_w1lo = (__nv_bfloat16*)p;
        cudaGetSymbolAddress(&p, g_w2hi); p_w2hi = (__nv_bfloat16*)p;
        cudaGetSymbolAddress(&p, g_w2lo); p_w2lo = (__nv_bfloat16*)p;
    }

    // fork: branch B (preprocessing + W2 prep) runs concurrently with
    // branch A (W1 prep + GEMM1) on the capture graph.
    cudaStream_t sB = 0;
    cudaEvent_t evRoot = 0, evB = 0;
    bool forked = false;
    if (cudaStreamCreateWithFlags(&sB, cudaStreamNonBlocking) == cudaSuccess &&
        cudaEventCreateWithFlags(&evRoot, cudaEventDisableTiming) == cudaSuccess &&
        cudaEventCreateWithFlags(&evB, cudaEventDisableTiming) == cudaSuccess) {
        forked = (cudaEventRecord(evRoot, 0) == cudaSuccess) &&
                 (cudaStreamWaitEvent(sB, evRoot, 0) == cudaSuccess);
    }
    cudaStream_t pre = forked ? sB : 0;

    // branch B: graph preprocessing + W2 prep
    k_zero_cnt<<<(n + 255) / 256, 256, 0, pre>>>(n);
    k_count<<<(e + 255) / 256, 256, 0, pre>>>(ei, e);
    int nb = (n + SCAN_CHUNK - 1) / SCAN_CHUNK;
    k_blocksum<<<nb, SCAN_T, 0, pre>>>(n);
    k_scanb<<<1, 32, 0, pre>>>();
    k_scatter<<<nb, SCAN_T, 0, pre>>>(n);
    k_fill<<<(e + 255) / 256, 256, 0, pre>>>(ei, e);
    k_prep_w<<<(CHID * COUT + 255) / 256, 256, 0, pre>>>(W2, p_w2hi, p_w2lo, CHID, COUT);

    // branch A (legacy stream): W1 prep + GEMM1
    k_prep_w<<<(CIN * CHID + 255) / 256, 256>>>(W1, p_w1hi, p_w1lo, CIN, CHID);
    k_mma<CHID, CIN><<<(n + 127) / 128, 256>>>(n, x, p_w1hi, p_w1lo, p_h1, p_dinv);

    // join before aggregation
    if (forked) {
        cudaEventRecord(evB, sB);
        cudaStreamWaitEvent(0, evB, 0);
    }

    // layer 1 aggregation, layer 2, decode (all on legacy stream)
    k_agg128<<<(n + 7) / 8, 256>>>(p_h1, b1, p_z1, n, 1);
    k_mma<COUT, CHID><<<(n + 127) / 128, 256>>>(n, p_z1, p_w2hi, p_w2lo, p_h2, p_dinv);
    k_agg64<<<(n + 7) / 8, 256>>>(p_h2, b2, p_z2, n, 0);
    k_decode<<<(l + 255) / 256, 256>>>(eli, out, l);

    // cleanup only when not capturing (destroying mid-capture invalidates it)
    cudaStreamCaptureStatus st = cudaStreamCaptureStatusNone;
    cudaStreamIsCapturing(0, &st);
    if (st == cudaStreamCaptureStatusNone) {
        if (sB)     cudaStreamDestroy(sB);
        if (evRoot) cudaEventDestroy(evRoot);
        if (evB)    cudaEventDestroy(evB);
    }
}

// round 9
// speedup vs baseline: 2.4863x; 1.0636x over previous
#include <cuda_runtime.h>
#include <cuda_bf16.h>
#include <cstdint>

// Problem constants (fixed by dataset)
#define NMAX 50000
#define EMAX 800000
#define CIN  512
#define CHID 128
#define COUT 64

// scan geometry
#define SCAN_T 256
#define SCAN_I 16
#define SCAN_CHUNK (SCAN_T*SCAN_I)                         // 4096
#define SCAN_NB ((NMAX + SCAN_CHUNK - 1)/SCAN_CHUNK)       // 13

// ---------------- device scratch (static, allocation-free) ----------------
__device__ int   g_cnt[NMAX];
__device__ int   g_offsets[NMAX+1];
__device__ int   g_cursor[NMAX];
__device__ int   g_col[EMAX];
__device__ float g_dinv[NMAX];
__device__ int   g_bsum[SCAN_NB];
__device__ int   g_bpre[SCAN_NB];
__device__ float g_h1[NMAX*CHID];
__device__ float g_z1[NMAX*CHID];
__device__ float g_h2[NMAX*COUT];
__device__ float g_z2[NMAX*COUT];
// W1 transposed to [N][K] as tf32 bit patterns
__device__ uint32_t g_w1t[CHID*CIN];
// W2 transposed to [N][K], split into bf16 hi/lo
__device__ __nv_bfloat16 g_w2hi[COUT*CHID];
__device__ __nv_bfloat16 g_w2lo[COUT*CHID];

// ---------------- graph preprocessing ----------------
__global__ void k_zero_cnt(int n) {
    int i = blockIdx.x * blockDim.x + threadIdx.x;
    if (i < n) g_cnt[i] = 0;
}

__global__ void k_count(const int* __restrict__ ei, int e) {
    int i = blockIdx.x * blockDim.x + threadIdx.x;
    if (i < e) atomicAdd(&g_cnt[ei[e + i]], 1);
}

__global__ void k_blocksum(int n) {
    __shared__ int sd[SCAN_T];
    int b = blockIdx.x, t = threadIdx.x;
    int base = b * SCAN_CHUNK + t * SCAN_I;
    int s = 0;
    #pragma unroll
    for (int i = 0; i < SCAN_I; i++) {
        int idx = base + i;
        if (idx < n) {
            int c = g_cnt[idx];
            s += c;
            g_dinv[idx] = rsqrtf((float)(c + 1));
        }
    }
    sd[t] = s;
    __syncthreads();
    #pragma unroll
    for (int off = SCAN_T / 2; off > 0; off >>= 1) {
        if (t < off) sd[t] += sd[t + off];
        __syncthreads();
    }
    if (t == 0) g_bsum[b] = sd[0];
}

__global__ void k_scanb() {
    if (threadIdx.x == 0) {
        int run = 0;
        for (int i = 0; i < SCAN_NB; i++) { g_bpre[i] = run; run += g_bsum[i]; }
    }
}

__global__ void k_scatter(int n) {
    __shared__ int sd[SCAN_T];
    int b = blockIdx.x, t = threadIdx.x;
    int base = b * SCAN_CHUNK + t * SCAN_I;
    int loc[SCAN_I];
    int s = 0;
    #pragma unroll
    for (int i = 0; i < SCAN_I; i++) {
        int idx = base + i;
        int c = (idx < n) ? g_cnt[idx] : 0;
        loc[i] = s;
        s += c;
    }
    sd[t] = s;
    __syncthreads();
    int v = s;
    for (int off = 1; off < SCAN_T; off <<= 1) {
        int u = (t >= off) ? sd[t - off] : 0;
        __syncthreads();
        sd[t] += u;
        __syncthreads();
    }
    int pre = sd[t] - v + g_bpre[b];
    #pragma unroll
    for (int i = 0; i < SCAN_I; i++) {
        int idx = base + i;
        if (idx < n) {
            int o = pre + loc[i];
            g_offsets[idx] = o;
            g_cursor[idx]  = o;
        }
    }
    if (b == gridDim.x - 1 && t == SCAN_T - 1) g_offsets[n] = pre + s;
}

__global__ void k_fill(const int* __restrict__ ei, int e) {
    int i = blockIdx.x * blockDim.x + threadIdx.x;
    if (i < e) {
        int src = ei[i];
        int dst = ei[e + i];
        int pos = atomicAdd(&g_cursor[dst], 1);
        g_col[pos] = src;
    }
}

// ---------------- helpers ----------------
__device__ __forceinline__ uint32_t f2tf32(float f) {
    uint32_t r;
    asm("cvt.rna.tf32.f32 %0, %1;" : "=r"(r) : "f"(f));
    return r;
}
__device__ __forceinline__ void split1(float a, __nv_bfloat16& hi, __nv_bfloat16& lo) {
    hi = __float2bfloat16(a);
    lo = __float2bfloat16(a - __bfloat162float(hi));
}
__device__ __forceinline__ void mma_tf32(float* d, const uint32_t* a, const uint32_t* b) {
    asm volatile(
        "mma.sync.aligned.m16n8k8.row.col.f32.tf32.tf32.f32 "
        "{%0,%1,%2,%3}, {%4,%5,%6,%7}, {%8,%9}, {%0,%1,%2,%3};"
        : "+f"(d[0]), "+f"(d[1]), "+f"(d[2]), "+f"(d[3])
        : "r"(a[0]), "r"(a[1]), "r"(a[2]), "r"(a[3]), "r"(b[0]), "r"(b[1]));
}
__device__ __forceinline__ uint32_t smem_u32(const void* p) {
    uint32_t a;
    asm("{ .reg .u64 t; cvta.to.shared.u64 t, %1; cvt.u32.u64 %0, t; }" : "=r"(a) : "l"(p));
    return a;
}
__device__ __forceinline__ void ldm_x4(uint32_t* r, uint32_t addr) {
    asm volatile("ldmatrix.sync.aligned.m8n8.x4.shared.b16 {%0,%1,%2,%3}, [%4];"
                 : "=r"(r[0]), "=r"(r[1]), "=r"(r[2]), "=r"(r[3]) : "r"(addr));
}
__device__ __forceinline__ void mma_bf16(float* d, const uint32_t* a, const uint32_t* b) {
    asm volatile(
        "mma.sync.aligned.m16n8k16.row.col.f32.bf16.bf16.f32 "
        "{%0,%1,%2,%3}, {%4,%5,%6,%7}, {%8,%9}, {%0,%1,%2,%3};"
        : "+f"(d[0]), "+f"(d[1]), "+f"(d[2]), "+f"(d[3])
        : "r"(a[0]), "r"(a[1]), "r"(a[2]), "r"(a[3]), "r"(b[0]), "r"(b[1]));
}

// ---------------- weight prep ----------------
// W: [K][N] fp32 -> Wt: [N][K] tf32 bits
__global__ void k_prep_w1(const float* __restrict__ W, uint32_t* __restrict__ Wt,
                          int K, int N)
{
    int i = blockIdx.x * blockDim.x + threadIdx.x;
    if (i < K * N) {
        int k = i / N, nn = i % N;
        Wt[(size_t)nn * K + k] = f2tf32(W[i]);
    }
}
// W: [K][N] fp32 -> Whi/Wlo: [N][K] bf16
__global__ void k_prep_w2(const float* __restrict__ W,
                          __nv_bfloat16* __restrict__ Whi,
                          __nv_bfloat16* __restrict__ Wlo, int K, int N)
{
    int i = blockIdx.x * blockDim.x + threadIdx.x;
    if (i < K * N) {
        int k = i / N, nn = i % N;
        __nv_bfloat16 hi, lo;
        split1(W[i], hi, lo);
        Whi[(size_t)nn * K + k] = hi;
        Wlo[(size_t)nn * K + k] = lo;
    }
}

// ---------------- TF32 single-pass tensor-core GEMM (layer 1) ----------------
// C[r, 0:BN] = (A @ W)[r, :] * dinv[r]; A: [M, K] fp32, Bt: [BN][K] tf32 bits.
// 256 threads, BM=128, BK=16 (2 k8 steps), warp grid 2(m) x 4(n).
template<int BN, int K>
__global__ __launch_bounds__(256)
void k_mma_tf32(int M, const float* __restrict__ A, const uint32_t* __restrict__ Bt,
                float* __restrict__ C, const float* __restrict__ dinv)
{
    const int BM = 128, BK = 16, LD = 20;   // stride 20 words: conflict-free frags
    const int WTN = BN / 4;                 // 32
    const int NT  = WTN / 8;                // 4
    const int BLD = (BN * 4) / 256;         // B float4-loads per thread

    __shared__ uint32_t sA[BM][LD];
    __shared__ uint32_t sB[BN][LD];

    int tid = threadIdx.x, wid = tid >> 5, lane = tid & 31;
    int wm = wid >> 2, wn = wid & 3;
    int rowBase = blockIdx.x * BM;
    int lg = lane >> 2;          // 0..7
    int lt = lane & 3;           // 0..3

    float acc[4][NT][4];
    #pragma unroll
    for (int mi = 0; mi < 4; mi++)
        #pragma unroll
        for (int ni = 0; ni < NT; ni++)
            #pragma unroll
            for (int q = 0; q < 4; q++) acc[mi][ni][q] = 0.f;

    int ar0 = tid >> 2;                     // 0..63
    int akq = (tid & 3) * 4;                // 0,4,8,12

    float4 fa[2];
    uint4  fb[BLD];

    // preload k0 = 0
    #pragma unroll
    for (int it = 0; it < 2; it++) {
        int gr = rowBase + ar0 + it * 64;
        fa[it] = make_float4(0.f, 0.f, 0.f, 0.f);
        if (gr < M) fa[it] = *reinterpret_cast<const float4*>(A + (size_t)gr * K + akq);
    }
    #pragma unroll
    for (int it = 0; it < BLD; it++) {
        int bn = ar0 + it * 64;
        fb[it] = *reinterpret_cast<const uint4*>(Bt + (size_t)bn * K + akq);
    }

    for (int k0 = 0; k0 < K; k0 += BK) {
        // store prefetched regs to SMEM (A converted to tf32)
        #pragma unroll
        for (int it = 0; it < 2; it++) {
            int r = ar0 + it * 64;
            uint4 v = make_uint4(f2tf32(fa[it].x), f2tf32(fa[it].y),
                                 f2tf32(fa[it].z), f2tf32(fa[it].w));
            *reinterpret_cast<uint4*>(&sA[r][akq]) = v;
        }
        #pragma unroll
        for (int it = 0; it < BLD; it++) {
            int bn = ar0 + it * 64;
            *reinterpret_cast<uint4*>(&sB[bn][akq]) = fb[it];
        }
        __syncthreads();

        // prefetch next slab
        if (k0 + BK < K) {
            #pragma unroll
            for (int it = 0; it < 2; it++) {
                int gr = rowBase + ar0 + it * 64;
                fa[it] = make_float4(0.f, 0.f, 0.f, 0.f);
                if (gr < M)
                    fa[it] = *reinterpret_cast<const float4*>(A + (size_t)gr * K + k0 + BK + akq);
            }
            #pragma unroll
            for (int it = 0; it < BLD; it++) {
                int bn = ar0 + it * 64;
                fb[it] = *reinterpret_cast<const uint4*>(Bt + (size_t)bn * K + k0 + BK + akq);
            }
        }

        // two k8 steps
        #pragma unroll
        for (int ks = 0; ks < 2; ks++) {
            int kb = ks * 8;
            uint32_t a[4][4];
            #pragma unroll
            for (int mi = 0; mi < 4; mi++) {
                int row = wm * 64 + mi * 16 + lg;
                a[mi][0] = sA[row][kb + lt];
                a[mi][1] = sA[row + 8][kb + lt];
                a[mi][2] = sA[row][kb + 4 + lt];
                a[mi][3] = sA[row + 8][kb + 4 + lt];
            }
            uint32_t b[NT][2];
            #pragma unroll
            for (int ni = 0; ni < NT; ni++) {
                int nn = wn * WTN + ni * 8 + lg;
                b[ni][0] = sB[nn][kb + lt];
                b[ni][1] = sB[nn][kb + 4 + lt];
            }
            #pragma unroll
            for (int mi = 0; mi < 4; mi++)
                #pragma unroll
                for (int ni = 0; ni < NT; ni++)
                    mma_tf32(acc[mi][ni], a[mi], b[ni]);
        }
        __syncthreads();
    }

    // epilogue: scale by dinv[row], store fp32
    #pragma unroll
    for (int mi = 0; mi < 4; mi++) {
        int r = rowBase + wm * 64 + mi * 16 + lg;
        #pragma unroll
        for (int ni = 0; ni < NT; ni++) {
            int cn = wn * WTN + ni * 8 + lt * 2;
            if (r < M) {
                float sc = dinv[r];
                float2 o = make_float2(acc[mi][ni][0] * sc, acc[mi][ni][1] * sc);
                *reinterpret_cast<float2*>(C + (size_t)r * BN + cn) = o;
            }
            if (r + 8 < M) {
                float sc = dinv[r + 8];
                float2 o = make_float2(acc[mi][ni][2] * sc, acc[mi][ni][3] * sc);
                *reinterpret_cast<float2*>(C + (size_t)(r + 8) * BN + cn) = o;
            }
        }
    }
}

// ---------------- split-precision bf16 tensor-core GEMM (layer 2) ----------
template<int BN, int K>
__global__ __launch_bounds__(256)
void k_mma(int M, const float* __restrict__ A,
           const __nv_bfloat16* __restrict__ Bhi,
           const __nv_bfloat16* __restrict__ Blo,
           float* __restrict__ C, const float* __restrict__ dinv)
{
    const int BM = 128, BK = 16;
    const int LDA = 24, LDB = 24;
    const int WTN = BN / 4;
    const int NT  = WTN / 8;

    __shared__ __nv_bfloat16 sAh[BM][LDA], sAl[BM][LDA];
    __shared__ __nv_bfloat16 sBh[BN][LDB], sBl[BN][LDB];

    int tid = threadIdx.x, wid = tid >> 5, lane = tid & 31;
    int wm = wid >> 2;
    int wn = wid & 3;
    int rowBase = blockIdx.x * BM;

    float acc[4][NT][4];
    #pragma unroll
    for (int mi = 0; mi < 4; mi++)
        #pragma unroll
        for (int ni = 0; ni < NT; ni++)
            #pragma unroll
            for (int q = 0; q < 4; q++) acc[mi][ni][q] = 0.f;

    int ar0 = tid >> 2;
    int akq = (tid & 3) * 4;
    int bn  = tid >> 1;
    int bkq = (tid & 1) * 8;
    bool bvalid = (tid < BN * 2);

    float4 fa[2];
    uint4  fbh, fbl;

    {
        #pragma unroll
        for (int it = 0; it < 2; it++) {
            int gr = rowBase + ar0 + it * 64;
            fa[it] = make_float4(0.f, 0.f, 0.f, 0.f);
            if (gr < M) fa[it] = *reinterpret_cast<const float4*>(A + (size_t)gr * K + akq);
        }
        if (bvalid) {
            fbh = *reinterpret_cast<const uint4*>(Bhi + (size_t)bn * K + bkq);
            fbl = *reinterpret_cast<const uint4*>(Blo + (size_t)bn * K + bkq);
        }
    }

    uint32_t sAh_base = smem_u32(&sAh[0][0]);
    uint32_t sAl_base = smem_u32(&sAl[0][0]);

    for (int k0 = 0; k0 < K; k0 += BK) {
        #pragma unroll
        for (int it = 0; it < 2; it++) {
            int r = ar0 + it * 64;
            __nv_bfloat16 h[4], l[4];
            split1(fa[it].x, h[0], l[0]);
            split1(fa[it].y, h[1], l[1]);
            split1(fa[it].z, h[2], l[2]);
            split1(fa[it].w, h[3], l[3]);
            *reinterpret_cast<uint2*>(&sAh[r][akq]) = *reinterpret_cast<uint2*>(h);
            *reinterpret_cast<uint2*>(&sAl[r][akq]) = *reinterpret_cast<uint2*>(l);
        }
        if (bvalid) {
            *reinterpret_cast<uint4*>(&sBh[bn][bkq]) = fbh;
            *reinterpret_cast<uint4*>(&sBl[bn][bkq]) = fbl;
        }
        __syncthreads();

        if (k0 + BK < K) {
            #pragma unroll
            for (int it = 0; it < 2; it++) {
                int gr = rowBase + ar0 + it * 64;
                fa[it] = make_float4(0.f, 0.f, 0.f, 0.f);
                if (gr < M)
                    fa[it] = *reinterpret_cast<const float4*>(A + (size_t)gr * K + k0 + BK + akq);
            }
            if (bvalid) {
                fbh = *reinterpret_cast<const uint4*>(Bhi + (size_t)bn * K + k0 + BK + bkq);
                fbl = *reinterpret_cast<const uint4*>(Blo + (size_t)bn * K + k0 + BK + bkq);
            }
        }

        uint32_t ah[4][4], al[4][4];
        int arow = wm * 64 + (lane & 15);
        int acol = (lane >> 4) * 8;
        #pragma unroll
        for (int mi = 0; mi < 4; mi++) {
            uint32_t off = (uint32_t)((arow + mi * 16) * LDA + acol) * 2;
            ldm_x4(ah[mi], sAh_base + off);
            ldm_x4(al[mi], sAl_base + off);
        }
        uint32_t bh[NT][2], bl[NT][2];
        int bn0 = wn * WTN + (lane >> 2);
        int bk  = (lane & 3) * 2;
        #pragma unroll
        for (int ni = 0; ni < NT; ni++) {
            bh[ni][0] = *reinterpret_cast<const uint32_t*>(&sBh[bn0 + ni * 8][bk]);
            bh[ni][1] = *reinterpret_cast<const uint32_t*>(&sBh[bn0 + ni * 8][bk + 8]);
            bl[ni][0] = *reinterpret_cast<const uint32_t*>(&sBl[bn0 + ni * 8][bk]);
            bl[ni][1] = *reinterpret_cast<const uint32_t*>(&sBl[bn0 + ni * 8][bk + 8]);
        }

        #pragma unroll
        for (int mi = 0; mi < 4; mi++)
            #pragma unroll
            for (int ni = 0; ni < NT; ni++) {
                mma_bf16(acc[mi][ni], ah[mi], bh[ni]);
                mma_bf16(acc[mi][ni], al[mi], bh[ni]);
                mma_bf16(acc[mi][ni], ah[mi], bl[ni]);
            }
        __syncthreads();
    }

    #pragma unroll
    for (int mi = 0; mi < 4; mi++) {
        int r = rowBase + wm * 64 + mi * 16 + (lane >> 2);
        #pragma unroll
        for (int ni = 0; ni < NT; ni++) {
            int cn = wn * WTN + ni * 8 + (lane & 3) * 2;
            if (r < M) {
                float sc = dinv[r];
                float2 o = make_float2(acc[mi][ni][0] * sc, acc[mi][ni][1] * sc);
                *reinterpret_cast<float2*>(C + (size_t)r * BN + cn) = o;
            }
            if (r + 8 < M) {
                float sc = dinv[r + 8];
                float2 o = make_float2(acc[mi][ni][2] * sc, acc[mi][ni][3] * sc);
                *reinterpret_cast<float2*>(C + (size_t)(r + 8) * BN + cn) = o;
            }
        }
    }
}

// ---------------- warp-per-node aggregation ----------------
__global__ __launch_bounds__(256)
void k_agg128(const float* __restrict__ h, const float* __restrict__ bias,
              float* __restrict__ z, int n, int do_relu)
{
    int node = blockIdx.x * 8 + (threadIdx.x >> 5);
    if (node >= n) return;
    int lane = threadIdx.x & 31;
    const float4* hb = reinterpret_cast<const float4*>(h);

    int beg = g_offsets[node];
    int end = g_offsets[node + 1];
    float4 acc = hb[(size_t)node * 32 + lane];

    int e = beg;
    for (; e + 4 <= end; e += 4) {
        int s0 = g_col[e], s1 = g_col[e+1], s2 = g_col[e+2], s3 = g_col[e+3];
        float4 v0 = hb[(size_t)s0 * 32 + lane];
        float4 v1 = hb[(size_t)s1 * 32 + lane];
        float4 v2 = hb[(size_t)s2 * 32 + lane];
        float4 v3 = hb[(size_t)s3 * 32 + lane];
        acc.x += v0.x + v1.x + v2.x + v3.x;
        acc.y += v0.y + v1.y + v2.y + v3.y;
        acc.z += v0.z + v1.z + v2.z + v3.z;
        acc.w += v0.w + v1.w + v2.w + v3.w;
    }
    for (; e < end; e++) {
        float4 v = hb[(size_t)g_col[e] * 32 + lane];
        acc.x += v.x; acc.y += v.y; acc.z += v.z; acc.w += v.w;
    }

    float di = g_dinv[node];
    float4 bb = reinterpret_cast<const float4*>(bias)[lane];
    acc.x = acc.x * di + bb.x;
    acc.y = acc.y * di + bb.y;
    acc.z = acc.z * di + bb.z;
    acc.w = acc.w * di + bb.w;
    if (do_relu) {
        acc.x = fmaxf(acc.x, 0.f); acc.y = fmaxf(acc.y, 0.f);
        acc.z = fmaxf(acc.z, 0.f); acc.w = fmaxf(acc.w, 0.f);
    }
    reinterpret_cast<float4*>(z)[(size_t)node * 32 + lane] = acc;
}

__global__ __launch_bounds__(256)
void k_agg64(const float* __restrict__ h, const float* __restrict__ bias,
             float* __restrict__ z, int n, int do_relu)
{
    int node = blockIdx.x * 8 + (threadIdx.x >> 5);
    if (node >= n) return;
    int lane = threadIdx.x & 31;
    const float2* hb = reinterpret_cast<const float2*>(h);

    int beg = g_offsets[node];
    int end = g_offsets[node + 1];
    float2 acc = hb[(size_t)node * 32 + lane];

    int e = beg;
    for (; e + 4 <= end; e += 4) {
        int s0 = g_col[e], s1 = g_col[e+1], s2 = g_col[e+2], s3 = g_col[e+3];
        float2 v0 = hb[(size_t)s0 * 32 + lane];
        float2 v1 = hb[(size_t)s1 * 32 + lane];
        float2 v2 = hb[(size_t)s2 * 32 + lane];
        float2 v3 = hb[(size_t)s3 * 32 + lane];
        acc.x += v0.x + v1.x + v2.x + v3.x;
        acc.y += v0.y + v1.y + v2.y + v3.y;
    }
    for (; e < end; e++) {
        float2 v = hb[(size_t)g_col[e] * 32 + lane];
        acc.x += v.x; acc.y += v.y;
    }

    float di = g_dinv[node];
    float2 bb = reinterpret_cast<const float2*>(bias)[lane];
    acc.x = acc.x * di + bb.x;
    acc.y = acc.y * di + bb.y;
    if (do_relu) { acc.x = fmaxf(acc.x, 0.f); acc.y = fmaxf(acc.y, 0.f); }
    reinterpret_cast<float2*>(z)[(size_t)node * 32 + lane] = acc;
}

// ---------------- decode ----------------
__global__ void k_decode(const int* __restrict__ eli, float* __restrict__ out, int l)
{
    int i = blockIdx.x * blockDim.x + threadIdx.x;
    if (i >= l) return;
    int es = eli[i];
    int ed = eli[l + i];
    const float4* a = reinterpret_cast<const float4*>(g_z2 + (size_t)es * COUT);
    const float4* b = reinterpret_cast<const float4*>(g_z2 + (size_t)ed * COUT);
    float s = 0.f;
    #pragma unroll
    for (int k = 0; k < COUT / 4; k++) {
        float4 va = a[k], vb = b[k];
        s += va.x * vb.x + va.y * vb.y + va.z * vb.z + va.w * vb.w;
    }
    out[i] = s;
}

extern "C" void kernel_launch(void* const* d_in, const int* in_sizes, int n_in,
                              void* d_out, int out_size)
{
    const float* x   = (const float*)d_in[0];
    const int*   ei  = (const int*)d_in[1];
    const int*   eli = (const int*)d_in[2];
    const float* W1  = (const float*)d_in[3];
    const float* b1  = (const float*)d_in[4];
    const float* W2  = (const float*)d_in[5];
    const float* b2  = (const float*)d_in[6];
    float*       out = (float*)d_out;

    int n = in_sizes[0] / CIN;   // 50000
    int e = in_sizes[1] / 2;     // 800000
    int l = in_sizes[2] / 2;     // 100000

    float *p_h1, *p_z1, *p_h2, *p_z2, *p_dinv;
    uint32_t* p_w1t;
    __nv_bfloat16 *p_w2hi, *p_w2lo;
    {
        void* p;
        cudaGetSymbolAddress(&p, g_h1);   p_h1   = (float*)p;
        cudaGetSymbolAddress(&p, g_z1);   p_z1   = (float*)p;
        cudaGetSymbolAddress(&p, g_h2);   p_h2   = (float*)p;
        cudaGetSymbolAddress(&p, g_z2);   p_z2   = (float*)p;
        cudaGetSymbolAddress(&p, g_dinv); p_dinv = (float*)p;
        cudaGetSymbolAddress(&p, g_w1t);  p_w1t  = (uint32_t*)p;
        cudaGetSymbolAddress(&p, g_w2hi); p_w2hi = (__nv_bfloat16*)p;
        cudaGetSymbolAddress(&p, g_w2lo); p_w2lo = (__nv_bfloat16*)p;
    }

    // fork: branch B (preprocessing + W2 prep) || branch A (W1 prep + GEMM1)
    cudaStream_t sB = 0;
    cudaEvent_t evRoot = 0, evB = 0;
    bool forked = false;
    if (cudaStreamCreateWithFlags(&sB, cudaStreamNonBlocking) == cudaSuccess &&
        cudaEventCreateWithFlags(&evRoot, cudaEventDisableTiming) == cudaSuccess &&
        cudaEventCreateWithFlags(&evB, cudaEventDisableTiming) == cudaSuccess) {
        forked = (cudaEventRecord(evRoot, 0) == cudaSuccess) &&
                 (cudaStreamWaitEvent(sB, evRoot, 0) == cudaSuccess);
    }
    cudaStream_t pre = forked ? sB : 0;

    // branch B: graph preprocessing + W2 prep
    k_zero_cnt<<<(n + 255) / 256, 256, 0, pre>>>(n);
    k_count<<<(e + 255) / 256, 256, 0, pre>>>(ei, e);
    int nb = (n + SCAN_CHUNK - 1) / SCAN_CHUNK;
    k_blocksum<<<nb, SCAN_T, 0, pre>>>(n);
    k_scanb<<<1, 32, 0, pre>>>();
    k_scatter<<<nb, SCAN_T, 0, pre>>>(n);
    k_fill<<<(e + 255) / 256, 256, 0, pre>>>(ei, e);
    k_prep_w2<<<(CHID * COUT + 255) / 256, 256, 0, pre>>>(W2, p_w2hi, p_w2lo, CHID, COUT);

    // branch A (legacy stream): W1 prep (tf32) + GEMM1 (tf32 single-pass)
    k_prep_w1<<<(CIN * CHID + 255) / 256, 256>>>(W1, p_w1t, CIN, CHID);
    k_mma_tf32<CHID, CIN><<<(n + 127) / 128, 256>>>(n, x, p_w1t, p_h1, p_dinv);

    // join before aggregation
    if (forked) {
        cudaEventRecord(evB, sB);
        cudaStreamWaitEvent(0, evB, 0);
    }

    // layer 1 aggregation, layer 2 (bf16 3-pass), decode
    k_agg128<<<(n + 7) / 8, 256>>>(p_h1, b1, p_z1, n, 1);
    k_mma<COUT, CHID><<<(n + 127) / 128, 256>>>(n, p_z1, p_w2hi, p_w2lo, p_h2, p_dinv);
    k_agg64<<<(n + 7) / 8, 256>>>(p_h2, b2, p_z2, n, 0);
    k_decode<<<(l + 255) / 256, 256>>>(eli, out, l);

    // cleanup only when not capturing
    cudaStreamCaptureStatus st = cudaStreamCaptureStatusNone;
    cudaStreamIsCapturing(0, &st);
    if (st == cudaStreamCaptureStatusNone) {
        if (sB)     cudaStreamDestroy(sB);
        if (evRoot) cudaEventDestroy(evRoot);
        if (evB)    cudaEventDestroy(evB);
    }
}